// round 3
// baseline (speedup 1.0000x reference)
#include <cuda_runtime.h>
#include <math.h>

// ---------------------------------------------------------------------------
// VectorQuantizer on GB300 (sm_103a) — R3: packed fp32 (fma.rn.f32x2 / FFMA2)
//   x:        [32, 256, 32, 32] f32  (NCHW)   -> flat rows n=(b,h,w), dim c=256
//   codebook: [1024, 256] f32
// Outputs (concatenated f32): [loss(1), q_out(8388608 NCHW), perplexity(1), idx(32768)]
//
// Key insight from R2 ncu: 3-reg FFMA has rt_SMSP=2 on sm_103a -> scalar SGEMM
// caps at 50% fp32. fma.rn.f32x2 (FFMA2) does 2 exact fp32 FMAs per issue.
// ---------------------------------------------------------------------------

#define NROWS   32768      // 32 * 32 * 32
#define NCODES  1024
#define CDIM    256
#define QELEMS  8388608    // 32*256*32*32
#define GATHER_BLOCKS 4096

typedef unsigned long long u64;

// packed f32x2 fma: d.lo += a.lo*b.lo ; d.hi += a.hi*b.hi  (exact per-lane IEEE fma)
#define FMA2(d, a, b) \
    asm("fma.rn.f32x2 %0, %1, %2, %0;" : "+l"(d) : "l"(a), "l"(b))

__device__ __forceinline__ void unpack2(u64 v, float& lo, float& hi) {
    asm("mov.b64 {%0, %1}, %2;" : "=f"(lo), "=f"(hi) : "l"(v));
}

// Scratch (no cudaMalloc allowed): __device__ globals
__device__ float g_srow[NROWS];            // ||x_n||^2
__device__ float g_cc[NCODES];             // ||c_k||^2
__device__ float g_cbT[CDIM * NCODES];     // codebook transposed [k-dim][code]
__device__ int   g_best[NROWS];            // argmin index per row
__device__ int   g_counts[NCODES];         // histogram
__device__ float g_partials[GATHER_BLOCKS];// per-block squared-error sums

// ---------------------------------------------------------------------------
__global__ void zero_kernel() {
    int t = blockIdx.x * blockDim.x + threadIdx.x;
    if (t < NCODES) g_counts[t] = 0;
    if (t < GATHER_BLOCKS) g_partials[t] = 0.0f;
}

// ||x_n||^2, coalesced across warp (consecutive n = consecutive hw)
__global__ void prep_s_kernel(const float* __restrict__ x) {
    int n = blockIdx.x * blockDim.x + threadIdx.x;   // grid covers 32768
    int b  = n >> 10;
    int hw = n & 1023;
    const float* p = x + (size_t)b * 262144 + hw;
    float s = 0.0f;
    #pragma unroll 8
    for (int c = 0; c < CDIM; c++) {
        float v = p[(size_t)c << 10];
        s = __fmaf_rn(v, v, s);
    }
    g_srow[n] = s;
}

// transpose codebook into g_cbT[k][code] and compute ||c||^2
__global__ void prep_cb_kernel(const float* __restrict__ cb) {
    __shared__ float sh[256];
    int k = blockIdx.x;          // code
    int t = threadIdx.x;         // dim
    float v = cb[k * CDIM + t];
    g_cbT[(size_t)t * NCODES + k] = v;
    sh[t] = v * v;
    __syncthreads();
    for (int s = 128; s > 0; s >>= 1) {
        if (t < s) sh[t] += sh[t + s];
        __syncthreads();
    }
    if (t == 0) g_cc[k] = sh[0];
}

// ---------------------------------------------------------------------------
// Main: per block, 128 rows x all 1024 codes. FFMA2-tiled f32 GEMM with fused
// argmin epilogue per 128-code tile.
//   block = 256 threads, tx = tid&15 (codes), ty = tid>>4 (rows)
//   per thread: 8 rows x 8 codes, held as acc[8][4] f32x2 (pairs over codes)
//   A tile stored DUPLICATED in shared: Asd[kk][2r]=Asd[kk][2r+1]=x_r, so
//   (a_i, a_i) pairs load directly; reads are ty-only -> full broadcast.
// ---------------------------------------------------------------------------
__global__ void __launch_bounds__(256, 2)
vq_main_kernel(const float* __restrict__ x) {
    __shared__ float Asd[16][264];  // [k][row duplicated x2], padded (1056B stride, 16B-aligned)
    __shared__ float Bs[16][132];   // [k][code], padded (528B stride, 16B-aligned)

    const int tid = threadIdx.x;
    const int tx  = tid & 15;
    const int ty  = tid >> 4;
    const int n0  = blockIdx.x * 128;
    const int b   = n0 >> 10;
    const int hw0 = n0 & 1023;                 // 128-aligned
    const float* xb = x + (size_t)b * 262144 + hw0;

    float sreg[8];
    #pragma unroll
    for (int i = 0; i < 8; i++) sreg[i] = g_srow[n0 + ty * 8 + i];

    float bestd[8];
    int   bestc[8];
    #pragma unroll
    for (int i = 0; i < 8; i++) { bestd[i] = 3.4e38f; bestc[i] = 0; }

    for (int ct = 0; ct < 8; ct++) {           // 8 code tiles of 128
        const int c0 = ct * 128;
        u64 acc[8][4];
        #pragma unroll
        for (int i = 0; i < 8; i++)
            #pragma unroll
            for (int j = 0; j < 4; j++) acc[i][j] = 0ull;

        for (int k0 = 0; k0 < CDIM; k0 += 16) {
            __syncthreads();
            // load A tile (128 rows x 16 k, duplicated) and B tile (128 codes x 16 k)
            #pragma unroll
            for (int t = 0; t < 2; t++) {
                int j  = tid + t * 256;        // [0,512)
                int kk = j >> 5;
                int r4 = (j & 31) * 4;
                float4 va = *(const float4*)(xb + r4 + (size_t)(k0 + kk) * 1024);
                *(float4*)&Asd[kk][2 * r4]     = make_float4(va.x, va.x, va.y, va.y);
                *(float4*)&Asd[kk][2 * r4 + 4] = make_float4(va.z, va.z, va.w, va.w);
                float4 vb = *(const float4*)(g_cbT + (size_t)(k0 + kk) * NCODES + c0 + r4);
                *(float4*)&Bs[kk][r4] = vb;
            }
            __syncthreads();

            #pragma unroll
            for (int kk = 0; kk < 16; kk++) {
                // A pairs: (a_i, a_i) for 8 rows -> 4x LDS.128 (broadcast across tx)
                ulonglong2 aA = *(const ulonglong2*)&Asd[kk][ty * 16];
                ulonglong2 aB = *(const ulonglong2*)&Asd[kk][ty * 16 + 4];
                ulonglong2 aC = *(const ulonglong2*)&Asd[kk][ty * 16 + 8];
                ulonglong2 aD = *(const ulonglong2*)&Asd[kk][ty * 16 + 12];
                // B pairs: (b_2j, b_2j+1) for 8 codes -> 2x LDS.128
                ulonglong2 b01 = *(const ulonglong2*)&Bs[kk][tx * 8];
                ulonglong2 b23 = *(const ulonglong2*)&Bs[kk][tx * 8 + 4];
                u64 aP[8] = {aA.x, aA.y, aB.x, aB.y, aC.x, aC.y, aD.x, aD.y};
                u64 bP[4] = {b01.x, b01.y, b23.x, b23.y};
                #pragma unroll
                for (int i = 0; i < 8; i++)
                    #pragma unroll
                    for (int jp = 0; jp < 4; jp++)
                        FMA2(acc[i][jp], aP[i], bP[jp]);
            }
        }

        // epilogue: d = (s + cc) - 2*dot  (explicit rounded ops, NO contraction —
        // must match the reference's rounding). Codes ascending: jp asc, lo then hi.
        #pragma unroll
        for (int jp = 0; jp < 4; jp++) {
            int cA = c0 + tx * 8 + 2 * jp;      // even code of the pair
            float ccA = g_cc[cA];
            float ccB = g_cc[cA + 1];
            #pragma unroll
            for (int i = 0; i < 8; i++) {
                float dotA, dotB;
                unpack2(acc[i][jp], dotA, dotB);
                float tA = __fadd_rn(sreg[i], ccA);
                float mA = __fmul_rn(2.0f, dotA);
                float dA = __fadd_rn(tA, -mA);
                if (dA < bestd[i]) { bestd[i] = dA; bestc[i] = cA; }
                float tB = __fadd_rn(sreg[i], ccB);
                float mB = __fmul_rn(2.0f, dotB);
                float dB = __fadd_rn(tB, -mB);
                if (dB < bestd[i]) { bestd[i] = dB; bestc[i] = cA + 1; }
            }
        }
    }

    // reduce across the 16 tx lanes sharing each row (lanes contiguous in
    // half-warps since tid = ty*16 + tx). Tie -> smaller index.
    #pragma unroll
    for (int i = 0; i < 8; i++) {
        float v = bestd[i];
        int   c = bestc[i];
        #pragma unroll
        for (int off = 8; off > 0; off >>= 1) {
            float vo = __shfl_down_sync(0xffffffffu, v, off);
            int   co = __shfl_down_sync(0xffffffffu, c, off);
            if (vo < v || (vo == v && co < c)) { v = vo; c = co; }
        }
        if (tx == 0) g_best[n0 + ty * 8 + i] = c;
    }
}

// ---------------------------------------------------------------------------
__global__ void hist_kernel() {
    int n = blockIdx.x * blockDim.x + threadIdx.x;   // 32768
    atomicAdd(&g_counts[g_best[n]], 1);
}

// gather quantized values, write q_out (straight-through value = x + (q - x)),
// accumulate squared error deterministically into g_partials
__global__ void gather_kernel(const float* __restrict__ x,
                              const float* __restrict__ cb,
                              float* __restrict__ out, long long q_off) {
    __shared__ float sh[256];
    long long stride = (long long)gridDim.x * blockDim.x;
    float part = 0.0f;
    for (long long o = (long long)blockIdx.x * blockDim.x + threadIdx.x;
         o < QELEMS; o += stride) {
        int b  = (int)(o >> 18);
        int c  = (int)((o >> 10) & 255);
        int hw = (int)(o & 1023);
        int n  = (b << 10) + hw;
        int idx = g_best[n];
        float q  = cb[idx * CDIM + c];
        float xo = x[o];
        float diff = __fadd_rn(q, -xo);          // q - x
        part = __fmaf_rn(diff, diff, part);
        if (q_off >= 0) out[q_off + o] = __fadd_rn(xo, diff);  // x + (q - x)
    }
    sh[threadIdx.x] = part;
    __syncthreads();
    for (int s = 128; s > 0; s >>= 1) {
        if (threadIdx.x < s) sh[threadIdx.x] += sh[threadIdx.x + s];
        __syncthreads();
    }
    if (threadIdx.x == 0) g_partials[blockIdx.x] = sh[0];
}

__global__ void idxout_kernel(float* __restrict__ out, long long idx_off) {
    int n = blockIdx.x * blockDim.x + threadIdx.x;
    out[idx_off + n] = (float)g_best[n];
}

__global__ void finalize_kernel(float* __restrict__ out,
                                long long loss_off, long long perp_off) {
    __shared__ float sh[1024];
    int t = threadIdx.x;
    float s = 0.0f;
    #pragma unroll
    for (int j = 0; j < GATHER_BLOCKS / 1024; j++)
        s += g_partials[t * (GATHER_BLOCKS / 1024) + j];
    sh[t] = s;
    __syncthreads();
    for (int st = 512; st > 0; st >>= 1) {
        if (t < st) sh[t] += sh[t + st];
        __syncthreads();
    }
    float total = sh[0];
    __syncthreads();

    // perplexity
    float p = (float)g_counts[t] / (float)NROWS;
    sh[t] = p * logf(p + 1e-10f);
    __syncthreads();
    for (int st = 512; st > 0; st >>= 1) {
        if (t < st) sh[t] += sh[t + st];
        __syncthreads();
    }
    if (t == 0) {
        if (loss_off >= 0) out[loss_off] = 1.25f * (total / (float)QELEMS);
        if (perp_off >= 0) out[perp_off] = expf(-sh[0]);
    }
}

// ---------------------------------------------------------------------------
extern "C" void kernel_launch(void* const* d_in, const int* in_sizes, int n_in,
                              void* d_out, int out_size) {
    const float* x  = (const float*)d_in[0];   // [32,256,32,32]
    const float* cb = (const float*)d_in[1];   // [1024,256]
    float* out = (float*)d_out;

    long long loss_off = -1, q_off = -1, perp_off = -1, idx_off = -1;
    if (out_size == 1 + QELEMS + 1 + NROWS) {
        loss_off = 0; q_off = 1; perp_off = 1 + QELEMS; idx_off = 2 + QELEMS;
    } else if (out_size == QELEMS) {
        q_off = 0;
    } else if (out_size == QELEMS + NROWS) {
        q_off = 0; idx_off = QELEMS;
    } else if (out_size == NROWS) {
        idx_off = 0;
    } else {
        // default: full concatenated layout
        loss_off = 0; q_off = 1; perp_off = 1 + QELEMS; idx_off = 2 + QELEMS;
    }

    zero_kernel<<<GATHER_BLOCKS / 256, 256>>>();
    prep_s_kernel<<<NROWS / 256, 256>>>(x);
    prep_cb_kernel<<<NCODES, 256>>>(cb);
    vq_main_kernel<<<NROWS / 128, 256>>>(x);
    hist_kernel<<<NROWS / 256, 256>>>();
    gather_kernel<<<GATHER_BLOCKS, 256>>>(x, cb, out, q_off);
    if (idx_off >= 0) idxout_kernel<<<NROWS / 256, 256>>>(out, idx_off);
    if (loss_off >= 0 || perp_off >= 0)
        finalize_kernel<<<1, 1024>>>(out, loss_off, perp_off);
}

// round 12
// speedup vs baseline: 1.1843x; 1.1843x over previous
#include <cuda_runtime.h>
#include <cuda_bf16.h>
#include <cstdint>
#include <math.h>

// ---------------------------------------------------------------------------
// VectorQuantizer on GB300 (sm_103a host; ptxas targets BASE sm_103).
// R11: 3-term bf16-split GEMM (HMMA) as CANDIDATE FILTER + exact fp32 rescore.
//   GEMM approx error <= 3.1e-5 (incl. rounding); margin 1e-4 guarantees the
//   true argmin (and all exact ties) are in the candidate set; rescore decides
//   with R2-proven fp32 math.
// ---------------------------------------------------------------------------

#define NROWS   32768
#define NCODES  1024
#define CDIM    256
#define QELEMS  8388608
#define GATHER_BLOCKS 4096
#define NRB     256            // row blocks of 128
#define NCB     4              // code blocks of 256
#define KT      24             // k-tiles of 32 (virtual K = 768)
#define MARGIN  1e-4f
#define CANDS   16             // candidate slots per (row, code-block)

typedef unsigned long long u64;
typedef unsigned int u32;
typedef unsigned short u16;

// ---- device scratch (static, no allocs) -----------------------------------
__device__ u16   g_A[NRB * 16 * 4096];   // [rb][slot 0-7:x1, 8-15:x2][128x32]
__device__ u16   g_B[NCB * 16 * 8192];   // [cb][slot 0-7:c1, 8-15:c2][256x32]
__device__ float g_xT[NROWS * CDIM];     // row-major fp32 x (for rescore)
__device__ float g_srow[NROWS];
__device__ float g_cc[NCODES];
__device__ int   g_ccnt[NROWS * NCB];    // candidate counts
__device__ u32   g_cand[NROWS * NCB * CANDS];
__device__ int   g_best[NROWS];
__device__ int   g_counts[NCODES];
__device__ float g_partials[GATHER_BLOCKS];

#define MMA_BF16(c, a, b) \
    asm volatile("mma.sync.aligned.m16n8k16.row.col.f32.bf16.bf16.f32 " \
                 "{%0,%1,%2,%3}, {%4,%5,%6,%7}, {%8,%9}, {%0,%1,%2,%3};" \
                 : "+f"((c)[0]), "+f"((c)[1]), "+f"((c)[2]), "+f"((c)[3]) \
                 : "r"((a)[0]), "r"((a)[1]), "r"((a)[2]), "r"((a)[3]), \
                   "r"((b)[0]), "r"((b)[1]))

// ---------------------------------------------------------------------------
__global__ void zero_kernel() {
    int t = blockIdx.x * blockDim.x + threadIdx.x;   // 32768 threads
    #pragma unroll
    for (int j = 0; j < NCB; j++) g_ccnt[t * NCB + j] = 0;
    if (t < NCODES) g_counts[t] = 0;
    if (t < GATHER_BLOCKS) g_partials[t] = 0.0f;
}

__global__ void prep_s_kernel(const float* __restrict__ x) {
    int n = blockIdx.x * blockDim.x + threadIdx.x;
    int b  = n >> 10;
    int hw = n & 1023;
    const float* p = x + (size_t)b * 262144 + hw;
    float s = 0.0f;
    #pragma unroll 8
    for (int c = 0; c < CDIM; c++) {
        float v = p[(size_t)c << 10];
        s = __fmaf_rn(v, v, s);
    }
    g_srow[n] = s;
}

__global__ void prep_cc_kernel(const float* __restrict__ cb) {
    __shared__ float sh[256];
    int k = blockIdx.x, t = threadIdx.x;
    float v = cb[k * CDIM + t];
    sh[t] = v * v;
    __syncthreads();
    for (int s = 128; s > 0; s >>= 1) {
        if (t < s) sh[t] += sh[t + s];
        __syncthreads();
    }
    if (t == 0) g_cc[k] = sh[0];
}

// ---- prep A: bf16 2-way split tiles + fp32 row-major xT -------------------
__global__ void __launch_bounds__(256)
prepA_kernel(const float* __restrict__ x) {
    __shared__ u16 s1[4096];
    __shared__ u16 s2[4096];
    __shared__ float sxf[4096];
    const int rb = blockIdx.x;
    const int b = rb >> 3;
    const int hw0 = (rb << 7) & 1023;
    const int t = threadIdx.x;
    const int r = t & 127;
    const int ch = (t >> 7) * 16;

    for (int w = 0; w < 8; w++) {
        #pragma unroll
        for (int j = 0; j < 16; j++) {
            int kk = ch + j;
            int c = w * 32 + kk;
            float v = x[((size_t)b << 18) + ((size_t)c << 10) + hw0 + r];
            __nv_bfloat16 x1 = __float2bfloat16(v);
            float r1 = __fadd_rn(v, -__bfloat162float(x1));
            __nv_bfloat16 x2 = __float2bfloat16(r1);
            s1[r * 32 + kk] = __bfloat16_as_ushort(x1);
            s2[r * 32 + kk] = __bfloat16_as_ushort(x2);
            sxf[r * 32 + kk] = v;
        }
        __syncthreads();
        uint4* d1 = (uint4*)(g_A + (size_t)(rb * 16 + w) * 4096);
        uint4* d2 = (uint4*)(g_A + (size_t)(rb * 16 + 8 + w) * 4096);
        d1[t] = ((uint4*)s1)[t];  d1[t + 256] = ((uint4*)s1)[t + 256];
        d2[t] = ((uint4*)s2)[t];  d2[t + 256] = ((uint4*)s2)[t + 256];
        // fp32 xT: row-major [n][256]; tile rows at rb*128, dims w*32..w*32+31
        float4* dx = (float4*)g_xT;
        #pragma unroll
        for (int j = 0; j < 4; j++) {
            int u = t + 256 * j;              // [0,1024) float4s
            int row = u >> 3, dc = u & 7;     // 8 float4 = 32 dims
            dx[(size_t)(rb * 128 + row) * 64 + w * 8 + dc] = ((float4*)sxf)[u];
        }
        __syncthreads();
    }
}

// ---- prep B: bf16 2-way split of codebook into 256x32 tiles ---------------
__global__ void __launch_bounds__(256)
prepB_kernel(const float* __restrict__ cb) {
    __shared__ u16 s1[8192];
    __shared__ u16 s2[8192];
    const int cq = blockIdx.x;
    const int t = threadIdx.x;
    for (int w = 0; w < 8; w++) {
        #pragma unroll
        for (int kk = 0; kk < 32; kk++) {
            float v = cb[(size_t)(cq * 256 + t) * 256 + w * 32 + kk];
            __nv_bfloat16 c1 = __float2bfloat16(v);
            float r1 = __fadd_rn(v, -__bfloat162float(c1));
            __nv_bfloat16 c2 = __float2bfloat16(r1);
            s1[t * 32 + kk] = __bfloat16_as_ushort(c1);
            s2[t * 32 + kk] = __bfloat16_as_ushort(c2);
        }
        __syncthreads();
        uint4* d1 = (uint4*)(g_B + (size_t)(cq * 16 + w) * 8192);
        uint4* d2 = (uint4*)(g_B + (size_t)(cq * 16 + 8 + w) * 8192);
        #pragma unroll
        for (int j = 0; j < 4; j++) {
            d1[t + 256 * j] = ((uint4*)s1)[t + 256 * j];
            d2[t + 256 * j] = ((uint4*)s2)[t + 256 * j];
        }
        __syncthreads();
    }
}

// ---------------------------------------------------------------------------
// GEMM filter: grid (4 cb, 256 rb), 512 thr. Identical mainloop to R10
// (validated: only 2 boundary flips). Epilogue now emits candidates.
// ---------------------------------------------------------------------------
__global__ void __launch_bounds__(512, 1)
vq_mma_kernel() {
    extern __shared__ char sm[];
    const int tid = threadIdx.x;
    const int lane = tid & 31;
    const int wid = tid >> 5;
    const int wm = wid >> 2;
    const int wn = wid & 3;
    const int cq = blockIdx.x;
    const int rb = blockIdx.y;
    const int r4 = lane >> 2;
    const int q  = lane & 3;

    float acc[2][8][4] = {};

    auto srcA = [&](int kt) {
        int akt = (kt < 8) ? kt : kt - 8;
        return (const uint4*)(g_A + (size_t)(rb * 16 + akt) * 4096);
    };
    auto srcB = [&](int kt) {
        int bkt = (kt < 16) ? kt : kt - 16;
        return (const uint4*)(g_B + (size_t)(cq * 16 + bkt) * 8192);
    };
    const u32 aOff = (u32)((tid >> 2) * 80 + (tid & 3) * 16);
    const u32 b0Off = aOff;
    const u32 b1Off = (u32)(((tid + 512) >> 2) * 80 + (tid & 3) * 16);

    uint4 rA, rB0, rB1;
    rA = srcA(0)[tid]; rB0 = srcB(0)[tid]; rB1 = srcB(0)[tid + 512];
    *(uint4*)(sm + 0     + aOff)  = rA;
    *(uint4*)(sm + 20480 + b0Off) = rB0;
    *(uint4*)(sm + 20480 + b1Off) = rB1;
    __syncthreads();

    for (int kt = 0; kt < KT; kt++) {
        const int buf = kt & 1;
        const bool more = (kt + 1 < KT);
        if (more) {
            rA = srcA(kt + 1)[tid];
            rB0 = srcB(kt + 1)[tid];
            rB1 = srcB(kt + 1)[tid + 512];
        }
        const char* sa = sm + buf * 10240;
        const char* sb = sm + 20480 + buf * 20480;
        #pragma unroll
        for (int ks = 0; ks < 32; ks += 16) {
            u32 a[2][4];
            #pragma unroll
            for (int t = 0; t < 2; t++) {
                int m0 = wm * 32 + t * 16;
                a[t][0] = *(const u32*)(sa + ((m0 + r4)     * 40 + ks +     2 * q) * 2);
                a[t][1] = *(const u32*)(sa + ((m0 + r4 + 8) * 40 + ks +     2 * q) * 2);
                a[t][2] = *(const u32*)(sa + ((m0 + r4)     * 40 + ks + 8 + 2 * q) * 2);
                a[t][3] = *(const u32*)(sa + ((m0 + r4 + 8) * 40 + ks + 8 + 2 * q) * 2);
            }
            u32 b[8][2];
            #pragma unroll
            for (int nt = 0; nt < 8; nt++) {
                int n = wn * 64 + nt * 8 + r4;
                b[nt][0] = *(const u32*)(sb + (n * 40 + ks +     2 * q) * 2);
                b[nt][1] = *(const u32*)(sb + (n * 40 + ks + 8 + 2 * q) * 2);
            }
            #pragma unroll
            for (int t = 0; t < 2; t++)
                #pragma unroll
                for (int nt = 0; nt < 8; nt++)
                    MMA_BF16(acc[t][nt], a[t], b[nt]);
        }
        __syncthreads();
        if (more) {
            const int nb = buf ^ 1;
            *(uint4*)(sm + nb * 10240 + aOff)          = rA;
            *(uint4*)(sm + 20480 + nb * 20480 + b0Off) = rB0;
            *(uint4*)(sm + 20480 + nb * 20480 + b1Off) = rB1;
            __syncthreads();
        }
    }
    __syncthreads();

    // ---- epilogue: approx d, CTA-local row min, candidate emission ---------
    float* scc  = (float*)sm;              // 256 floats
    float* lmin = (float*)(sm + 1024);     // 128 rows x 4 wn
    if (tid < 256) scc[tid] = g_cc[cq * 256 + tid];
    __syncthreads();

    // pass 1: per-(row) warp-local min over this warp's 64 codes
    #pragma unroll
    for (int t = 0; t < 2; t++) {
        #pragma unroll
        for (int sub = 0; sub < 2; sub++) {
            int row = wm * 32 + t * 16 + sub * 8 + r4;
            float s = g_srow[rb * 128 + row];
            float bestd = 3.4e38f;
            #pragma unroll
            for (int nt = 0; nt < 8; nt++) {
                #pragma unroll
                for (int e = 0; e < 2; e++) {
                    int cl = wn * 64 + nt * 8 + 2 * q + e;
                    float t2 = __fadd_rn(s, scc[cl]);
                    float m  = __fmul_rn(2.0f, acc[t][nt][sub * 2 + e]);
                    float d  = __fadd_rn(t2, -m);
                    if (d < bestd) bestd = d;
                }
            }
            #pragma unroll
            for (int off = 1; off <= 2; off <<= 1) {
                float vo = __shfl_xor_sync(0xffffffffu, bestd, off);
                if (vo < bestd) bestd = vo;
            }
            if (q == 0) lmin[row * 4 + wn] = bestd;
        }
    }
    __syncthreads();

    // pass 2: threshold = CTA-local row min + margin; emit candidates
    #pragma unroll
    for (int t = 0; t < 2; t++) {
        #pragma unroll
        for (int sub = 0; sub < 2; sub++) {
            int row = wm * 32 + t * 16 + sub * 8 + r4;
            int n = rb * 128 + row;
            float s = g_srow[n];
            float thr = fminf(fminf(lmin[row * 4], lmin[row * 4 + 1]),
                              fminf(lmin[row * 4 + 2], lmin[row * 4 + 3])) + MARGIN;
            #pragma unroll
            for (int nt = 0; nt < 8; nt++) {
                #pragma unroll
                for (int e = 0; e < 2; e++) {
                    int cl = wn * 64 + nt * 8 + 2 * q + e;
                    float t2 = __fadd_rn(s, scc[cl]);
                    float m  = __fmul_rn(2.0f, acc[t][nt][sub * 2 + e]);
                    float d  = __fadd_rn(t2, -m);
                    if (d <= thr) {
                        int slot = atomicAdd(&g_ccnt[n * NCB + cq], 1);
                        if (slot < CANDS)
                            g_cand[(n * NCB + cq) * CANDS + slot] = (u32)(cq * 256 + cl);
                    }
                }
            }
        }
    }
}

// ---------------------------------------------------------------------------
// Exact rescore: one warp per row; fp32 dot (fma chain + shfl butterfly),
// d = (s + cc) - 2*dot with reference rounding; tie -> smaller code.
// ---------------------------------------------------------------------------
__global__ void __launch_bounds__(256)
rescore_kernel(const float* __restrict__ cb) {
    const int wid = threadIdx.x >> 5;
    const int lane = threadIdx.x & 31;
    const int n = blockIdx.x * 8 + wid;

    float xr[8];
    #pragma unroll
    for (int j = 0; j < 8; j++) xr[j] = g_xT[(size_t)n * 256 + j * 32 + lane];
    const float s = g_srow[n];

    int cnt[NCB];
    bool ovf = false;
    #pragma unroll
    for (int cbk = 0; cbk < NCB; cbk++) {
        cnt[cbk] = g_ccnt[n * NCB + cbk];
        if (cnt[cbk] > CANDS) ovf = true;
    }

    float bd = 3.4e38f;
    int bc = 0x7fffffff;
    auto eval = [&](int code) {
        const float* cp = cb + (size_t)code * 256;
        float p = 0.0f;
        #pragma unroll
        for (int j = 0; j < 8; j++) p = __fmaf_rn(xr[j], cp[j * 32 + lane], p);
        #pragma unroll
        for (int off = 16; off > 0; off >>= 1)
            p = __fadd_rn(p, __shfl_xor_sync(0xffffffffu, p, off));
        float t2 = __fadd_rn(s, g_cc[code]);
        float d  = __fadd_rn(t2, -__fmul_rn(2.0f, p));
        if (d < bd || (d == bd && code < bc)) { bd = d; bc = code; }
    };

    if (ovf) {
        for (int code = 0; code < NCODES; code++) eval(code);
    } else {
        #pragma unroll
        for (int cbk = 0; cbk < NCB; cbk++)
            for (int i = 0; i < cnt[cbk]; i++)
                eval((int)g_cand[(n * NCB + cbk) * CANDS + i]);
    }
    if (lane == 0) g_best[n] = bc;
}

// ---------------------------------------------------------------------------
__global__ void hist_kernel() {
    int n = blockIdx.x * blockDim.x + threadIdx.x;
    atomicAdd(&g_counts[g_best[n]], 1);
}

__global__ void gather_kernel(const float* __restrict__ x,
                              const float* __restrict__ cb,
                              float* __restrict__ out, long long q_off) {
    __shared__ float sh[256];
    long long stride = (long long)gridDim.x * blockDim.x;
    float part = 0.0f;
    for (long long o = (long long)blockIdx.x * blockDim.x + threadIdx.x;
         o < QELEMS; o += stride) {
        int b  = (int)(o >> 18);
        int c  = (int)((o >> 10) & 255);
        int hw = (int)(o & 1023);
        int n  = (b << 10) + hw;
        int idx = g_best[n];
        float q  = cb[idx * CDIM + c];
        float xo = x[o];
        float diff = __fadd_rn(q, -xo);
        part = __fmaf_rn(diff, diff, part);
        if (q_off >= 0) out[q_off + o] = __fadd_rn(xo, diff);
    }
    sh[threadIdx.x] = part;
    __syncthreads();
    for (int s = 128; s > 0; s >>= 1) {
        if (threadIdx.x < s) sh[threadIdx.x] += sh[threadIdx.x + s];
        __syncthreads();
    }
    if (threadIdx.x == 0) g_partials[blockIdx.x] = sh[0];
}

__global__ void idxout_kernel(float* __restrict__ out, long long idx_off) {
    int n = blockIdx.x * blockDim.x + threadIdx.x;
    out[idx_off + n] = (float)g_best[n];
}

__global__ void finalize_kernel(float* __restrict__ out,
                                long long loss_off, long long perp_off) {
    __shared__ float sh[1024];
    int t = threadIdx.x;
    float s = 0.0f;
    #pragma unroll
    for (int j = 0; j < GATHER_BLOCKS / 1024; j++)
        s += g_partials[t * (GATHER_BLOCKS / 1024) + j];
    sh[t] = s;
    __syncthreads();
    for (int st = 512; st > 0; st >>= 1) {
        if (t < st) sh[t] += sh[t + st];
        __syncthreads();
    }
    float total = sh[0];
    __syncthreads();
    float p = (float)g_counts[t] / (float)NROWS;
    sh[t] = p * logf(p + 1e-10f);
    __syncthreads();
    for (int st = 512; st > 0; st >>= 1) {
        if (t < st) sh[t] += sh[t + st];
        __syncthreads();
    }
    if (t == 0) {
        if (loss_off >= 0) out[loss_off] = 1.25f * (total / (float)QELEMS);
        if (perp_off >= 0) out[perp_off] = expf(-sh[0]);
    }
}

// ---------------------------------------------------------------------------
extern "C" void kernel_launch(void* const* d_in, const int* in_sizes, int n_in,
                              void* d_out, int out_size) {
    const float* x  = (const float*)d_in[0];
    const float* cb = (const float*)d_in[1];
    float* out = (float*)d_out;

    long long loss_off = -1, q_off = -1, perp_off = -1, idx_off = -1;
    if (out_size == 1 + QELEMS + 1 + NROWS) {
        loss_off = 0; q_off = 1; perp_off = 1 + QELEMS; idx_off = 2 + QELEMS;
    } else if (out_size == QELEMS) {
        q_off = 0;
    } else if (out_size == QELEMS + NROWS) {
        q_off = 0; idx_off = QELEMS;
    } else if (out_size == NROWS) {
        idx_off = 0;
    } else {
        loss_off = 0; q_off = 1; perp_off = 1 + QELEMS; idx_off = 2 + QELEMS;
    }

    cudaFuncSetAttribute(vq_mma_kernel,
                         cudaFuncAttributeMaxDynamicSharedMemorySize, 61440);

    zero_kernel<<<NROWS / 256, 256>>>();
    prep_s_kernel<<<NROWS / 256, 256>>>(x);
    prepA_kernel<<<NRB, 256>>>(x);
    prepB_kernel<<<NCB, 256>>>(cb);
    prep_cc_kernel<<<NCODES, 256>>>(cb);
    dim3 grid(NCB, NRB);
    vq_mma_kernel<<<grid, 512, 61440>>>();
    rescore_kernel<<<NROWS / 8, 256>>>(cb);
    hist_kernel<<<NROWS / 256, 256>>>();
    gather_kernel<<<GATHER_BLOCKS, 256>>>(x, cb, out, q_off);
    if (idx_off >= 0) idxout_kernel<<<NROWS / 256, 256>>>(out, idx_off);
    if (loss_off >= 0 || perp_off >= 0)
        finalize_kernel<<<1, 1024>>>(out, loss_off, perp_off);
}

// round 16
// speedup vs baseline: 2.0903x; 1.7650x over previous
#include <cuda_runtime.h>
#include <cuda_bf16.h>
#include <cstdint>
#include <math.h>

// ---------------------------------------------------------------------------
// VectorQuantizer on GB300 (sm_103a host; ptxas targets BASE sm_103).
// R13: SINGLE-term bf16 GEMM (HMMA) candidate filter + exact fp32 rescore.
//   Filter error (incl. bf16 residuals + fp32 rounding) ~8e-5 rms; margin
//   4e-4 (~12 sigma) keeps the true argmin in the candidate set; exact
//   rescore (R2-proven math) decides. GEMM K=256 (was 768) -> 3x less work.
//   prepB re-gridded 4->32 CTAs (was 80.7us at occ 12.5%).
// ---------------------------------------------------------------------------

#define NROWS   32768
#define NCODES  1024
#define CDIM    256
#define QELEMS  8388608
#define GATHER_BLOCKS 4096
#define NRB     256            // row blocks of 128
#define NCB     4              // code blocks of 256
#define KT      8              // k-tiles of 32 (K = 256, single bf16 term)
#define MARGIN  4e-4f
#define CANDS   16             // candidate slots per (row, code-block)

typedef unsigned long long u64;
typedef unsigned int u32;
typedef unsigned short u16;

// ---- device scratch (static, no allocs) -----------------------------------
__device__ u16   g_A[NRB * KT * 4096];   // [rb][kt][128x32] bf16(x)   (16.8MB)
__device__ u16   g_B[NCB * KT * 8192];   // [cb][kt][256x32] bf16(c)   (0.5MB)
__device__ float g_xT[NROWS * CDIM];     // row-major fp32 x (rescore)
__device__ float g_srow[NROWS];
__device__ float g_cc[NCODES];
__device__ int   g_ccnt[NROWS * NCB];    // candidate counts
__device__ u32   g_cand[NROWS * NCB * CANDS];
__device__ int   g_best[NROWS];
__device__ int   g_counts[NCODES];
__device__ float g_partials[GATHER_BLOCKS];

#define MMA_BF16(c, a, b) \
    asm volatile("mma.sync.aligned.m16n8k16.row.col.f32.bf16.bf16.f32 " \
                 "{%0,%1,%2,%3}, {%4,%5,%6,%7}, {%8,%9}, {%0,%1,%2,%3};" \
                 : "+f"((c)[0]), "+f"((c)[1]), "+f"((c)[2]), "+f"((c)[3]) \
                 : "r"((a)[0]), "r"((a)[1]), "r"((a)[2]), "r"((a)[3]), \
                   "r"((b)[0]), "r"((b)[1]))

// ---------------------------------------------------------------------------
__global__ void zero_kernel() {
    int t = blockIdx.x * blockDim.x + threadIdx.x;   // 32768 threads
    #pragma unroll
    for (int j = 0; j < NCB; j++) g_ccnt[t * NCB + j] = 0;
    if (t < NCODES) g_counts[t] = 0;
    if (t < GATHER_BLOCKS) g_partials[t] = 0.0f;
}

__global__ void prep_s_kernel(const float* __restrict__ x) {
    int n = blockIdx.x * blockDim.x + threadIdx.x;
    int b  = n >> 10;
    int hw = n & 1023;
    const float* p = x + (size_t)b * 262144 + hw;
    float s = 0.0f;
    #pragma unroll 8
    for (int c = 0; c < CDIM; c++) {
        float v = p[(size_t)c << 10];
        s = __fmaf_rn(v, v, s);
    }
    g_srow[n] = s;
}

__global__ void prep_cc_kernel(const float* __restrict__ cb) {
    __shared__ float sh[256];
    int k = blockIdx.x, t = threadIdx.x;
    float v = cb[k * CDIM + t];
    sh[t] = v * v;
    __syncthreads();
    for (int s = 128; s > 0; s >>= 1) {
        if (t < s) sh[t] += sh[t + s];
        __syncthreads();
    }
    if (t == 0) g_cc[k] = sh[0];
}

// ---- prep A: bf16(x) tiles + fp32 row-major xT ----------------------------
__global__ void __launch_bounds__(256)
prepA_kernel(const float* __restrict__ x) {
    __shared__ u16 s1[4096];
    __shared__ float sxf[4096];
    const int rb = blockIdx.x;
    const int b = rb >> 3;
    const int hw0 = (rb << 7) & 1023;
    const int t = threadIdx.x;
    const int r = t & 127;
    const int ch = (t >> 7) * 16;

    for (int w = 0; w < KT; w++) {
        #pragma unroll
        for (int j = 0; j < 16; j++) {
            int kk = ch + j;
            int c = w * 32 + kk;
            float v = x[((size_t)b << 18) + ((size_t)c << 10) + hw0 + r];
            s1[r * 32 + kk] = __bfloat16_as_ushort(__float2bfloat16(v));
            sxf[r * 32 + kk] = v;
        }
        __syncthreads();
        uint4* d1 = (uint4*)(g_A + (size_t)(rb * KT + w) * 4096);
        d1[t] = ((uint4*)s1)[t];  d1[t + 256] = ((uint4*)s1)[t + 256];
        float4* dx = (float4*)g_xT;
        #pragma unroll
        for (int j = 0; j < 4; j++) {
            int u = t + 256 * j;              // [0,1024) float4s
            int row = u >> 3, dc = u & 7;
            dx[(size_t)(rb * 128 + row) * 64 + w * 8 + dc] = ((float4*)sxf)[u];
        }
        __syncthreads();
    }
}

// ---- prep B: bf16(codebook) tiles; grid 32 = (cbk, w), coalesced ----------
__global__ void __launch_bounds__(256)
prepB_kernel(const float* __restrict__ cb) {
    __shared__ u16 s1[8192];
    const int cbk = blockIdx.x >> 3;   // code block
    const int w   = blockIdx.x & 7;    // k-window
    const int t = threadIdx.x;
    #pragma unroll
    for (int j = 0; j < 32; j++) {
        int u = t + 256 * j;                 // [0,8192)
        int code = u >> 5, kk = u & 31;      // warp reads one 128B code row
        float v = cb[(size_t)(cbk * 256 + code) * 256 + w * 32 + kk];
        s1[code * 32 + kk] = __bfloat16_as_ushort(__float2bfloat16(v));
    }
    __syncthreads();
    uint4* d1 = (uint4*)(g_B + (size_t)(cbk * KT + w) * 8192);
    #pragma unroll
    for (int j = 0; j < 4; j++)
        d1[t + 256 * j] = ((uint4*)s1)[t + 256 * j];
}

// ---------------------------------------------------------------------------
// GEMM filter: grid (4 cb, 256 rb), 512 thr (4x4 warps, warp tile 32x64).
// Register-staged double buffer; smem stride 40 u16 -> conflict-free LDS.
// smem: A0@0 A1@10240 B0@20480 B1@40960 (61440B)
// ---------------------------------------------------------------------------
__global__ void __launch_bounds__(512, 1)
vq_mma_kernel() {
    extern __shared__ char sm[];
    const int tid = threadIdx.x;
    const int lane = tid & 31;
    const int wid = tid >> 5;
    const int wm = wid >> 2;
    const int wn = wid & 3;
    const int cq = blockIdx.x;
    const int rb = blockIdx.y;
    const int r4 = lane >> 2;
    const int q  = lane & 3;

    float acc[2][8][4] = {};

    auto srcA = [&](int kt) {
        return (const uint4*)(g_A + (size_t)(rb * KT + kt) * 4096);
    };
    auto srcB = [&](int kt) {
        return (const uint4*)(g_B + (size_t)(cq * KT + kt) * 8192);
    };
    const u32 aOff = (u32)((tid >> 2) * 80 + (tid & 3) * 16);
    const u32 b0Off = aOff;
    const u32 b1Off = (u32)(((tid + 512) >> 2) * 80 + (tid & 3) * 16);

    uint4 rA, rB0, rB1;
    rA = srcA(0)[tid]; rB0 = srcB(0)[tid]; rB1 = srcB(0)[tid + 512];
    *(uint4*)(sm + 0     + aOff)  = rA;
    *(uint4*)(sm + 20480 + b0Off) = rB0;
    *(uint4*)(sm + 20480 + b1Off) = rB1;
    __syncthreads();

    for (int kt = 0; kt < KT; kt++) {
        const int buf = kt & 1;
        const bool more = (kt + 1 < KT);
        if (more) {
            rA = srcA(kt + 1)[tid];
            rB0 = srcB(kt + 1)[tid];
            rB1 = srcB(kt + 1)[tid + 512];
        }
        const char* sa = sm + buf * 10240;
        const char* sb = sm + 20480 + buf * 20480;
        #pragma unroll
        for (int ks = 0; ks < 32; ks += 16) {
            u32 a[2][4];
            #pragma unroll
            for (int t = 0; t < 2; t++) {
                int m0 = wm * 32 + t * 16;
                a[t][0] = *(const u32*)(sa + ((m0 + r4)     * 40 + ks +     2 * q) * 2);
                a[t][1] = *(const u32*)(sa + ((m0 + r4 + 8) * 40 + ks +     2 * q) * 2);
                a[t][2] = *(const u32*)(sa + ((m0 + r4)     * 40 + ks + 8 + 2 * q) * 2);
                a[t][3] = *(const u32*)(sa + ((m0 + r4 + 8) * 40 + ks + 8 + 2 * q) * 2);
            }
            u32 b[8][2];
            #pragma unroll
            for (int nt = 0; nt < 8; nt++) {
                int n = wn * 64 + nt * 8 + r4;
                b[nt][0] = *(const u32*)(sb + (n * 40 + ks +     2 * q) * 2);
                b[nt][1] = *(const u32*)(sb + (n * 40 + ks + 8 + 2 * q) * 2);
            }
            #pragma unroll
            for (int t = 0; t < 2; t++)
                #pragma unroll
                for (int nt = 0; nt < 8; nt++)
                    MMA_BF16(acc[t][nt], a[t], b[nt]);
        }
        __syncthreads();
        if (more) {
            const int nb = buf ^ 1;
            *(uint4*)(sm + nb * 10240 + aOff)          = rA;
            *(uint4*)(sm + 20480 + nb * 20480 + b0Off) = rB0;
            *(uint4*)(sm + 20480 + nb * 20480 + b1Off) = rB1;
            __syncthreads();
        }
    }
    __syncthreads();

    // ---- epilogue: approx d, CTA-local row min, candidate emission ---------
    float* scc  = (float*)sm;              // 256 floats
    float* lmin = (float*)(sm + 1024);     // 128 rows x 4 wn
    if (tid < 256) scc[tid] = g_cc[cq * 256 + tid];
    __syncthreads();

    #pragma unroll
    for (int t = 0; t < 2; t++) {
        #pragma unroll
        for (int sub = 0; sub < 2; sub++) {
            int row = wm * 32 + t * 16 + sub * 8 + r4;
            float s = g_srow[rb * 128 + row];
            float bestd = 3.4e38f;
            #pragma unroll
            for (int nt = 0; nt < 8; nt++) {
                #pragma unroll
                for (int e = 0; e < 2; e++) {
                    int cl = wn * 64 + nt * 8 + 2 * q + e;
                    float t2 = __fadd_rn(s, scc[cl]);
                    float m  = __fmul_rn(2.0f, acc[t][nt][sub * 2 + e]);
                    float d  = __fadd_rn(t2, -m);
                    if (d < bestd) bestd = d;
                }
            }
            #pragma unroll
            for (int off = 1; off <= 2; off <<= 1) {
                float vo = __shfl_xor_sync(0xffffffffu, bestd, off);
                if (vo < bestd) bestd = vo;
            }
            if (q == 0) lmin[row * 4 + wn] = bestd;
        }
    }
    __syncthreads();

    #pragma unroll
    for (int t = 0; t < 2; t++) {
        #pragma unroll
        for (int sub = 0; sub < 2; sub++) {
            int row = wm * 32 + t * 16 + sub * 8 + r4;
            int n = rb * 128 + row;
            float s = g_srow[n];
            float thr = fminf(fminf(lmin[row * 4], lmin[row * 4 + 1]),
                              fminf(lmin[row * 4 + 2], lmin[row * 4 + 3])) + MARGIN;
            #pragma unroll
            for (int nt = 0; nt < 8; nt++) {
                #pragma unroll
                for (int e = 0; e < 2; e++) {
                    int cl = wn * 64 + nt * 8 + 2 * q + e;
                    float t2 = __fadd_rn(s, scc[cl]);
                    float m  = __fmul_rn(2.0f, acc[t][nt][sub * 2 + e]);
                    float d  = __fadd_rn(t2, -m);
                    if (d <= thr) {
                        int slot = atomicAdd(&g_ccnt[n * NCB + cq], 1);
                        if (slot < CANDS)
                            g_cand[(n * NCB + cq) * CANDS + slot] = (u32)(cq * 256 + cl);
                    }
                }
            }
        }
    }
}

// ---------------------------------------------------------------------------
// Exact rescore: one warp per row; fp32 dot + butterfly; tie -> smaller code.
// ---------------------------------------------------------------------------
__global__ void __launch_bounds__(256)
rescore_kernel(const float* __restrict__ cb) {
    const int wid = threadIdx.x >> 5;
    const int lane = threadIdx.x & 31;
    const int n = blockIdx.x * 8 + wid;

    float xr[8];
    #pragma unroll
    for (int j = 0; j < 8; j++) xr[j] = g_xT[(size_t)n * 256 + j * 32 + lane];
    const float s = g_srow[n];

    int cnt[NCB];
    bool ovf = false;
    #pragma unroll
    for (int cbk = 0; cbk < NCB; cbk++) {
        cnt[cbk] = g_ccnt[n * NCB + cbk];
        if (cnt[cbk] > CANDS) ovf = true;
    }

    float bd = 3.4e38f;
    int bc = 0x7fffffff;
    auto eval = [&](int code) {
        const float* cp = cb + (size_t)code * 256;
        float p = 0.0f;
        #pragma unroll
        for (int j = 0; j < 8; j++) p = __fmaf_rn(xr[j], cp[j * 32 + lane], p);
        #pragma unroll
        for (int off = 16; off > 0; off >>= 1)
            p = __fadd_rn(p, __shfl_xor_sync(0xffffffffu, p, off));
        float t2 = __fadd_rn(s, g_cc[code]);
        float d  = __fadd_rn(t2, -__fmul_rn(2.0f, p));
        if (d < bd || (d == bd && code < bc)) { bd = d; bc = code; }
    };

    if (ovf) {
        for (int code = 0; code < NCODES; code++) eval(code);
    } else {
        #pragma unroll
        for (int cbk = 0; cbk < NCB; cbk++)
            for (int i = 0; i < cnt[cbk]; i++)
                eval((int)g_cand[(n * NCB + cbk) * CANDS + i]);
    }
    if (lane == 0) g_best[n] = bc;
}

// ---------------------------------------------------------------------------
__global__ void hist_kernel() {
    int n = blockIdx.x * blockDim.x + threadIdx.x;
    atomicAdd(&g_counts[g_best[n]], 1);
}

__global__ void gather_kernel(const float* __restrict__ x,
                              const float* __restrict__ cb,
                              float* __restrict__ out, long long q_off) {
    __shared__ float sh[256];
    long long stride = (long long)gridDim.x * blockDim.x;
    float part = 0.0f;
    for (long long o = (long long)blockIdx.x * blockDim.x + threadIdx.x;
         o < QELEMS; o += stride) {
        int b  = (int)(o >> 18);
        int c  = (int)((o >> 10) & 255);
        int hw = (int)(o & 1023);
        int n  = (b << 10) + hw;
        int idx = g_best[n];
        float q  = cb[idx * CDIM + c];
        float xo = x[o];
        float diff = __fadd_rn(q, -xo);
        part = __fmaf_rn(diff, diff, part);
        if (q_off >= 0) out[q_off + o] = __fadd_rn(xo, diff);
    }
    sh[threadIdx.x] = part;
    __syncthreads();
    for (int s = 128; s > 0; s >>= 1) {
        if (threadIdx.x < s) sh[threadIdx.x] += sh[threadIdx.x + s];
        __syncthreads();
    }
    if (threadIdx.x == 0) g_partials[blockIdx.x] = sh[0];
}

__global__ void idxout_kernel(float* __restrict__ out, long long idx_off) {
    int n = blockIdx.x * blockDim.x + threadIdx.x;
    out[idx_off + n] = (float)g_best[n];
}

__global__ void finalize_kernel(float* __restrict__ out,
                                long long loss_off, long long perp_off) {
    __shared__ float sh[1024];
    int t = threadIdx.x;
    float s = 0.0f;
    #pragma unroll
    for (int j = 0; j < GATHER_BLOCKS / 1024; j++)
        s += g_partials[t * (GATHER_BLOCKS / 1024) + j];
    sh[t] = s;
    __syncthreads();
    for (int st = 512; st > 0; st >>= 1) {
        if (t < st) sh[t] += sh[t + st];
        __syncthreads();
    }
    float total = sh[0];
    __syncthreads();
    float p = (float)g_counts[t] / (float)NROWS;
    sh[t] = p * logf(p + 1e-10f);
    __syncthreads();
    for (int st = 512; st > 0; st >>= 1) {
        if (t < st) sh[t] += sh[t + st];
        __syncthreads();
    }
    if (t == 0) {
        if (loss_off >= 0) out[loss_off] = 1.25f * (total / (float)QELEMS);
        if (perp_off >= 0) out[perp_off] = expf(-sh[0]);
    }
}

// ---------------------------------------------------------------------------
extern "C" void kernel_launch(void* const* d_in, const int* in_sizes, int n_in,
                              void* d_out, int out_size) {
    const float* x  = (const float*)d_in[0];
    const float* cb = (const float*)d_in[1];
    float* out = (float*)d_out;

    long long loss_off = -1, q_off = -1, perp_off = -1, idx_off = -1;
    if (out_size == 1 + QELEMS + 1 + NROWS) {
        loss_off = 0; q_off = 1; perp_off = 1 + QELEMS; idx_off = 2 + QELEMS;
    } else if (out_size == QELEMS) {
        q_off = 0;
    } else if (out_size == QELEMS + NROWS) {
        q_off = 0; idx_off = QELEMS;
    } else if (out_size == NROWS) {
        idx_off = 0;
    } else {
        loss_off = 0; q_off = 1; perp_off = 1 + QELEMS; idx_off = 2 + QELEMS;
    }

    cudaFuncSetAttribute(vq_mma_kernel,
                         cudaFuncAttributeMaxDynamicSharedMemorySize, 61440);

    zero_kernel<<<NROWS / 256, 256>>>();
    prep_s_kernel<<<NROWS / 256, 256>>>(x);
    prepA_kernel<<<NRB, 256>>>(x);
    prepB_kernel<<<NCB * KT, 256>>>(cb);
    prep_cc_kernel<<<NCODES, 256>>>(cb);
    dim3 grid(NCB, NRB);
    vq_mma_kernel<<<grid, 512, 61440>>>();
    rescore_kernel<<<NROWS / 8, 256>>>(cb);
    hist_kernel<<<NROWS / 256, 256>>>();
    gather_kernel<<<GATHER_BLOCKS, 256>>>(x, cb, out, q_off);
    if (idx_off >= 0) idxout_kernel<<<NROWS / 256, 256>>>(out, idx_off);
    if (loss_off >= 0 || perp_off >= 0)
        finalize_kernel<<<1, 1024>>>(out, loss_off, perp_off);
}